// round 3
// baseline (speedup 1.0000x reference)
#include <cuda_runtime.h>
#include <math.h>

#define D       20
#define K1      30
#define KP      32          // padded K1
#define NRELP1  201
#define NTIME   365
#define NB      (3 * NRELP1)   // 603 buckets = (sel, rel)
#define NLAYERS 3
#define MAXN    1000000
#define EMAX    2000000

// ---------------- scratch (device globals; no runtime allocation) ----------------
__device__ __align__(16) float g_buf0[MAXN * D];            // 80 MB
__device__ __align__(16) float g_buf1[MAXN * D];            // 80 MB
__device__ __align__(16) float g_PbP[NRELP1 * KP];          // rela part of att MLP (padded)
__device__ __align__(16) float g_PcP[NRELP1 * KP];          // qrel part of att MLP (padded)
__device__ __align__(16) float g_RW[3 * NRELP1 * D];        // rela @ W_s^T
__device__ __align__(16) float g_TW[3 * NTIME * D];         // time @ W_s^T
__device__ __align__(16) float g_S0[NRELP1 * NRELP1];       // layer-0 sigmoid scores
__device__ __align__(16) int2  g_ebuf[EMAX];                // sorted packed edges (16 MB)
__device__ int g_hist[NB];
__device__ int g_off[NB + 1];
__device__ int g_cur[NB];

// vectorized global float4 reduction (sm_90+)
__device__ __forceinline__ void red_add_v4(float* addr, float a, float b, float c, float d) {
    asm volatile(
        "{ .reg .u64 p; cvta.to.global.u64 p, %0;\n\t"
        "  red.global.add.v4.f32 [p], {%1, %2, %3, %4}; }\n\t"
        :: "l"(addr), "f"(a), "f"(b), "f"(c), "f"(d) : "memory");
}

__device__ __forceinline__ float leaky(float x) { return x > 0.f ? x : 0.01f * x; }

__device__ __forceinline__ int bfind(const int* off, int idx) {
    int lo = 0, hi = NB;                 // off[0]=0 .. off[NB]=E
    while (hi - lo > 1) {
        int m = (lo + hi) >> 1;
        if (off[m] <= idx) lo = m; else hi = m;
    }
    return lo;
}

// ---------------- table precompute ----------------
__global__ void k_tables(const float* __restrict__ rela, const float* __restrict__ tem,
                         const float* __restrict__ w1,
                         const float* __restrict__ wp, const float* __restrict__ wn,
                         const float* __restrict__ wf)
{
    int i = blockIdx.x * blockDim.x + threadIdx.x;
    const int NPB = NRELP1 * KP;                 // 6432
    const int NRW = 3 * NRELP1 * D;              // 12060
    const int NTW = 3 * NTIME * D;               // 21900
    if (i < NPB) {
        int r = i / KP, k = i % KP;
        float a = 0.f;
        if (k < K1) {
            #pragma unroll
            for (int j = 0; j < D; j++) a = fmaf(rela[r * D + j], w1[k * (3 * D) + D + j], a);
        }
        g_PbP[i] = a;
    } else if (i < 2 * NPB) {
        int t = i - NPB;
        int r = t / KP, k = t % KP;
        float a = 0.f;
        if (k < K1) {
            #pragma unroll
            for (int j = 0; j < D; j++) a = fmaf(rela[r * D + j], w1[k * (3 * D) + 2 * D + j], a);
        }
        g_PcP[t] = a;
    } else if (i < 2 * NPB + NRW) {
        int t = i - 2 * NPB;
        int s = t / (NRELP1 * D);
        int rem = t % (NRELP1 * D);
        int r = rem / D, o = rem % D;
        const float* W = (s == 0) ? wp : ((s == 1) ? wn : wf);
        float a = 0.f;
        #pragma unroll
        for (int j = 0; j < D; j++) a = fmaf(rela[r * D + j], W[o * D + j], a);
        g_RW[t] = a;
    } else if (i < 2 * NPB + NRW + NTW) {
        int t = i - 2 * NPB - NRW;
        int s = t / (NTIME * D);
        int rem = t % (NTIME * D);
        int tt = rem / D, o = rem % D;
        const float* W = (s == 0) ? wp : ((s == 1) ? wn : wf);
        float a = 0.f;
        #pragma unroll
        for (int j = 0; j < D; j++) a = fmaf(tem[tt * D + j], W[o * D + j], a);
        g_TW[t] = a;
    }
}

// layer-0 score table: h_src = 0 -> score depends only on (rel, qrel)
__global__ void k_s0(const float* __restrict__ w2)
{
    int i = blockIdx.x * blockDim.x + threadIdx.x;
    if (i >= NRELP1 * NRELP1) return;
    int r = i / NRELP1, q = i % NRELP1;
    float s = 0.f;
    #pragma unroll
    for (int k = 0; k < K1; k++) {
        float a = g_PbP[r * KP + k] + g_PcP[q * KP + k];
        a = fmaxf(a, 0.f);
        s = fmaf(a, w2[k], s);
    }
    g_S0[i] = 1.f / (1.f + __expf(-s));
}

// ---------------- counting sort by (sel, rel): hist / scan / scatter ----------------
__global__ __launch_bounds__(256) void k_hist(
    const int* __restrict__ rel, const int* __restrict__ rtime, int E)
{
    __shared__ int sh[NB];
    for (int i = threadIdx.x; i < NB; i += blockDim.x) sh[i] = 0;
    __syncthreads();
    int e = blockIdx.x * blockDim.x + threadIdx.x;
    if (e < E) {
        int t = rtime[e];
        int sel = (t > 0) ? 2 : ((t == 0) ? 1 : 0);
        atomicAdd(&sh[sel * NRELP1 + rel[e]], 1);
    }
    __syncthreads();
    for (int i = threadIdx.x; i < NB; i += blockDim.x)
        if (sh[i]) atomicAdd(&g_hist[i], sh[i]);
}

__global__ void k_scan(int E)   // single block, 1024 threads
{
    __shared__ int sc[1024];
    int tid = threadIdx.x;
    sc[tid] = (tid < NB) ? g_hist[tid] : 0;
    __syncthreads();
    #pragma unroll
    for (int offs = 1; offs < 1024; offs <<= 1) {
        int v = (tid >= offs) ? sc[tid - offs] : 0;
        __syncthreads();
        sc[tid] += v;
        __syncthreads();
    }
    if (tid < NB) {
        int ex = (tid == 0) ? 0 : sc[tid - 1];
        g_off[tid] = ex;
        g_cur[tid] = ex;
    }
    if (tid == 0) g_off[NB] = E;
}

__global__ __launch_bounds__(256) void k_scat(
    const int* __restrict__ src, const int* __restrict__ dst,
    const int* __restrict__ rel, const int* __restrict__ qrel,
    const int* __restrict__ rtime, int E)
{
    int e = blockIdx.x * blockDim.x + threadIdx.x;
    if (e >= E) return;
    int t = rtime[e];
    int sel = (t > 0) ? 2 : ((t == 0) ? 1 : 0);
    int ta = t < 0 ? -t : t;
    int b = sel * NRELP1 + rel[e];
    int pos = atomicAdd(&g_cur[b], 1);
    g_ebuf[pos] = make_int2((int)((unsigned)src[e] | ((unsigned)qrel[e] << 20)),
                            (int)((unsigned)dst[e] | ((unsigned)ta << 20)));
}

// ---------------- layer 0 (sorted): hidden == 0, gather/scale/scatter, 4 edges/thread ----
__global__ __launch_bounds__(256) void k_edge0s(float* __restrict__ hout, int E)
{
    __shared__ int soff[NB + 1];
    for (int i = threadIdx.x; i < NB + 1; i += blockDim.x) soff[i] = g_off[i];
    __syncthreads();

    int t = blockIdx.x * blockDim.x + threadIdx.x;
    int e4 = t * 4;
    if (e4 >= E) return;
    int4 A = ((const int4*)g_ebuf)[2 * t];
    int4 Bv = ((const int4*)g_ebuf)[2 * t + 1];
    unsigned pw0[4] = {(unsigned)A.x, (unsigned)A.z, (unsigned)Bv.x, (unsigned)Bv.z};
    unsigned pw1[4] = {(unsigned)A.y, (unsigned)A.w, (unsigned)Bv.y, (unsigned)Bv.w};

    int bk = bfind(soff, e4);
    float score[4];
    const float4* rwp[4];
    const float4* twp[4];
    float* outp[4];
    #pragma unroll
    for (int e = 0; e < 4; e++) {
        while (bk < NB - 1 && soff[bk + 1] <= e4 + e) bk++;
        int sel = bk / NRELP1, rl = bk - sel * NRELP1;
        int q  = (int)(pw0[e] >> 20);
        int dn = (int)(pw1[e] & 0xFFFFFu);
        int ta = (int)(pw1[e] >> 20);
        score[e] = g_S0[rl * NRELP1 + q];
        if (e4 + e >= E) score[e] = 0.f;
        rwp[e] = (const float4*)(g_RW + (sel * NRELP1 + rl) * D);
        twp[e] = (const float4*)(g_TW + (sel * NTIME + ta) * D);
        outp[e] = hout + (size_t)dn * D;
    }
    #pragma unroll
    for (int g = 0; g < D / 4; g++) {
        #pragma unroll
        for (int e = 0; e < 4; e++) {
            float4 a = rwp[e][g];
            float4 b = twp[e][g];
            float sc = score[e];
            red_add_v4(outp[e] + 4 * g,
                       sc * (a.x + b.x), sc * (a.y + b.y),
                       sc * (a.z + b.z), sc * (a.w + b.w));
        }
    }
}

// ---------------- generic layer (sorted by (sel,rel)), 4 edges/thread ----------------
__global__ __launch_bounds__(256) void k_edge4s(
    const float* __restrict__ hin, float* __restrict__ hout,
    const float* __restrict__ w1, const float* __restrict__ w2,
    const float* __restrict__ wp, const float* __restrict__ wn,
    const float* __restrict__ wf, int E)
{
    __shared__ __align__(16) float sw1a[KP * D];   // w_att1[:, 0:20], rows 30/31 zero
    __shared__ float sw2s[KP];
    __shared__ __align__(16) float sW[3 * D * D];  // past / now / future
    __shared__ int soff[NB + 1];
    for (int i = threadIdx.x; i < KP * D; i += blockDim.x) {
        int k = i / D, j = i % D;
        sw1a[i] = (k < K1) ? w1[k * (3 * D) + j] : 0.f;
    }
    for (int i = threadIdx.x; i < KP; i += blockDim.x)
        sw2s[i] = (i < K1) ? w2[i] : 0.f;
    for (int i = threadIdx.x; i < 3 * D * D; i += blockDim.x) {
        int s = i / (D * D); int rem = i % (D * D);
        sW[i] = ((s == 0) ? wp : ((s == 1) ? wn : wf))[rem];
    }
    for (int i = threadIdx.x; i < NB + 1; i += blockDim.x) soff[i] = g_off[i];
    __syncthreads();

    int t = blockIdx.x * blockDim.x + threadIdx.x;
    int e4 = t * 4;
    if (e4 >= E) return;
    int4 A = ((const int4*)g_ebuf)[2 * t];
    int4 Bv = ((const int4*)g_ebuf)[2 * t + 1];
    unsigned pw0[4] = {(unsigned)A.x, (unsigned)A.z, (unsigned)Bv.x, (unsigned)Bv.z};
    unsigned pw1[4] = {(unsigned)A.y, (unsigned)A.w, (unsigned)Bv.y, (unsigned)Bv.w};

    int sn[4], dn[4], rl[4], ql[4], ta[4], sl[4];
    bool tail[4];
    int bk = bfind(soff, e4);
    #pragma unroll
    for (int e = 0; e < 4; e++) {
        while (bk < NB - 1 && soff[bk + 1] <= e4 + e) bk++;
        sl[e] = bk / NRELP1;
        rl[e] = bk - sl[e] * NRELP1;
        sn[e] = (int)(pw0[e] & 0xFFFFFu);
        ql[e] = (int)(pw0[e] >> 20);
        dn[e] = (int)(pw1[e] & 0xFFFFFu);
        ta[e] = (int)(pw1[e] >> 20);
        tail[e] = (e4 + e >= E);
    }

    // gather + fused leaky_relu
    float h[4][D];
    #pragma unroll
    for (int e = 0; e < 4; e++) {
        const float4* hp = (const float4*)(hin + (size_t)sn[e] * D);
        #pragma unroll
        for (int i = 0; i < D / 4; i++) {
            float4 v = hp[i];
            h[e][4 * i + 0] = leaky(v.x);
            h[e][4 * i + 1] = leaky(v.y);
            h[e][4 * i + 2] = leaky(v.z);
            h[e][4 * i + 3] = leaky(v.w);
        }
    }

    // attention: a_k = h . w1a_k + Pb[rel][k] + Pc[qrel][k]; score = sigmoid(relu(a) . w2)
    float sacc[4] = {0.f, 0.f, 0.f, 0.f};
    {
        const float4* pbp[4];
        const float4* pcp[4];
        #pragma unroll
        for (int e = 0; e < 4; e++) {
            pbp[e] = (const float4*)(g_PbP + rl[e] * KP);   // warp-uniform row (broadcast)
            pcp[e] = (const float4*)(g_PcP + ql[e] * KP);   // random row
        }
        #pragma unroll
        for (int g = 0; g < KP / 4; g++) {
            float4 pb4[4], pc4[4];
            #pragma unroll
            for (int e = 0; e < 4; e++) { pb4[e] = pbp[e][g]; pc4[e] = pcp[e][g]; }
            #pragma unroll
            for (int c = 0; c < 4; c++) {
                int k = g * 4 + c;
                const float4* wr = (const float4*)(sw1a + k * D);
                float w[D];
                #pragma unroll
                for (int i = 0; i < D / 4; i++) {
                    float4 v = wr[i];
                    w[4 * i + 0] = v.x; w[4 * i + 1] = v.y;
                    w[4 * i + 2] = v.z; w[4 * i + 3] = v.w;
                }
                float w2k = sw2s[k];
                #pragma unroll
                for (int e = 0; e < 4; e++) {
                    float a = ((const float*)&pb4[e])[c] + ((const float*)&pc4[e])[c];
                    #pragma unroll
                    for (int j = 0; j < D; j++) a = fmaf(h[e][j], w[j], a);
                    sacc[e] = fmaf(fmaxf(a, 0.f), w2k, sacc[e]);
                }
            }
        }
    }
    float score[4];
    #pragma unroll
    for (int e = 0; e < 4; e++) {
        score[e] = tail[e] ? 0.f : (1.f / (1.f + __expf(-sacc[e])));
    }

    // transformed = h @ W_sel^T + RW + TW ; msg = score * transformed; scatter
    const float4* rwp[4];
    const float4* twp[4];
    float* outp[4];
    #pragma unroll
    for (int e = 0; e < 4; e++) {
        rwp[e] = (const float4*)(g_RW + (sl[e] * NRELP1 + rl[e]) * D);
        twp[e] = (const float4*)(g_TW + (sl[e] * NTIME + ta[e]) * D);
        outp[e] = hout + (size_t)dn[e] * D;
    }
    bool uni = (sl[0] == sl[1]) & (sl[1] == sl[2]) & (sl[2] == sl[3]);
    if (uni) {
        const float* Wb = sW + sl[0] * D * D;
        #pragma unroll
        for (int g = 0; g < D / 4; g++) {
            float4 rt[4];
            #pragma unroll
            for (int e = 0; e < 4; e++) {
                float4 a = rwp[e][g];
                float4 b = twp[e][g];
                rt[e] = make_float4(a.x + b.x, a.y + b.y, a.z + b.z, a.w + b.w);
            }
            float mv[4][4];
            #pragma unroll
            for (int c = 0; c < 4; c++) {
                int i = g * 4 + c;
                const float4* wr = (const float4*)(Wb + i * D);
                float w[D];
                #pragma unroll
                for (int ii = 0; ii < D / 4; ii++) {
                    float4 v = wr[ii];
                    w[4 * ii + 0] = v.x; w[4 * ii + 1] = v.y;
                    w[4 * ii + 2] = v.z; w[4 * ii + 3] = v.w;
                }
                #pragma unroll
                for (int e = 0; e < 4; e++) {
                    float acc = ((const float*)&rt[e])[c];
                    #pragma unroll
                    for (int j = 0; j < D; j++) acc = fmaf(h[e][j], w[j], acc);
                    mv[e][c] = score[e] * acc;
                }
            }
            #pragma unroll
            for (int e = 0; e < 4; e++)
                red_add_v4(outp[e] + 4 * g, mv[e][0], mv[e][1], mv[e][2], mv[e][3]);
        }
    } else {
        // rare path: sel differs inside the batch (bucket boundary)
        #pragma unroll
        for (int e = 0; e < 4; e++) {
            const float* Wb = sW + sl[e] * D * D;
            #pragma unroll
            for (int g = 0; g < D / 4; g++) {
                float4 a = rwp[e][g];
                float4 b = twp[e][g];
                float rt[4] = {a.x + b.x, a.y + b.y, a.z + b.z, a.w + b.w};
                float mv[4];
                #pragma unroll
                for (int c = 0; c < 4; c++) {
                    int i = g * 4 + c;
                    float acc = rt[c];
                    #pragma unroll
                    for (int j = 0; j < D; j++) acc = fmaf(h[e][j], Wb[i * D + j], acc);
                    mv[c] = score[e] * acc;
                }
                red_add_v4(outp[e] + 4 * g, mv[0], mv[1], mv[2], mv[3]);
            }
        }
    }
}

// ---------------- final: leaky -> dot(w_cls) + b -> scatter ----------------
__global__ __launch_bounds__(256) void k_final(
    const float* __restrict__ hin, const int* __restrict__ nb,
    const int* __restrict__ ne, const float* __restrict__ wcls,
    const float* __restrict__ bcls, const int* __restrict__ pne,
    float* __restrict__ out, int n)
{
    int i = blockIdx.x * blockDim.x + threadIdx.x;
    if (i >= n) return;
    const float4* hp = (const float4*)(hin + (size_t)i * D);
    float acc = bcls[0];
    #pragma unroll
    for (int g = 0; g < D / 4; g++) {
        float4 v = hp[g];
        acc = fmaf(leaky(v.x), __ldg(wcls + 4 * g + 0), acc);
        acc = fmaf(leaky(v.y), __ldg(wcls + 4 * g + 1), acc);
        acc = fmaf(leaky(v.z), __ldg(wcls + 4 * g + 2), acc);
        acc = fmaf(leaky(v.w), __ldg(wcls + 4 * g + 3), acc);
    }
    long long idx = (long long)nb[i] * (long long)pne[0] + (long long)ne[i];
    out[idx] = acc;
}

// ---------------- host ----------------
extern "C" void kernel_launch(void* const* d_in, const int* in_sizes, int n_in,
                              void* d_out, int out_size)
{
    const int*   src   = (const int*)d_in[0];
    const int*   dst   = (const int*)d_in[1];
    const int*   rel   = (const int*)d_in[2];
    const int*   qrel  = (const int*)d_in[3];
    const int*   rtime = (const int*)d_in[4];
    const int*   nb    = (const int*)d_in[5];
    const int*   ne    = (const int*)d_in[6];
    const float* rela  = (const float*)d_in[7];
    const float* tem   = (const float*)d_in[8];
    const float* w1    = (const float*)d_in[9];
    const float* w2    = (const float*)d_in[10];
    const float* wp    = (const float*)d_in[11];
    const float* wn    = (const float*)d_in[12];
    const float* wf    = (const float*)d_in[13];
    const float* wcls  = (const float*)d_in[14];
    const float* bcls  = (const float*)d_in[15];
    const int*   pne   = (const int*)d_in[17];

    int E  = in_sizes[0] / NLAYERS;
    int Nn = in_sizes[5];

    float *b0, *b1;
    int *histp;
    cudaGetSymbolAddress((void**)&b0, g_buf0);
    cudaGetSymbolAddress((void**)&b1, g_buf1);
    cudaGetSymbolAddress((void**)&histp, g_hist);
    size_t bufBytes = (size_t)Nn * D * sizeof(float);

    // precompute tables (independent of hidden state)
    const int NTAB = 2 * NRELP1 * KP + 3 * NRELP1 * D + 3 * NTIME * D;
    k_tables<<<(NTAB + 255) / 256, 256>>>(rela, tem, w1, wp, wn, wf);
    k_s0<<<(NRELP1 * NRELP1 + 255) / 256, 256>>>(w2);

    int gE  = (E + 255) / 256;
    int gE4 = (E / 4 + 255) / 256;

    // ---- layer 0: sort by (sel, rel), then h=0 fast kernel into buf1 ----
    cudaMemsetAsync(histp, 0, NB * sizeof(int));
    k_hist<<<gE, 256>>>(rel, rtime, E);
    k_scan<<<1, 1024>>>(E);
    k_scat<<<gE, 256>>>(src, dst, rel, qrel, rtime, E);
    cudaMemsetAsync(b1, 0, bufBytes);
    k_edge0s<<<gE4, 256>>>(b1, E);

    // ---- layer 1: sort, read act(buf1) -> accumulate buf0 ----
    cudaMemsetAsync(histp, 0, NB * sizeof(int));
    k_hist<<<gE, 256>>>(rel + E, rtime + E, E);
    k_scan<<<1, 1024>>>(E);
    k_scat<<<gE, 256>>>(src + E, dst + E, rel + E, qrel + E, rtime + E, E);
    cudaMemsetAsync(b0, 0, bufBytes);
    k_edge4s<<<gE4, 256>>>(b1, b0, w1, w2, wp, wn, wf, E);

    // ---- layer 2: sort, read act(buf0) -> accumulate buf1 ----
    cudaMemsetAsync(histp, 0, NB * sizeof(int));
    k_hist<<<gE, 256>>>(rel + 2 * E, rtime + 2 * E, E);
    k_scan<<<1, 1024>>>(E);
    k_scat<<<gE, 256>>>(src + 2 * E, dst + 2 * E, rel + 2 * E, qrel + 2 * E, rtime + 2 * E, E);
    cudaMemsetAsync(b1, 0, bufBytes);
    k_edge4s<<<gE4, 256>>>(b0, b1, w1, w2, wp, wn, wf, E);

    // ---- output: zero then scatter ----
    cudaMemsetAsync(d_out, 0, (size_t)out_size * sizeof(float));
    k_final<<<(Nn + 255) / 256, 256>>>(b1, nb, ne, wcls, bcls, pne, (float*)d_out, Nn);
}